// round 14
// baseline (speedup 1.0000x reference)
#include <cuda_runtime.h>
#include <cstdint>

// FSMN depthwise strided FIR on GB300 — R14.
// R13 economics (2 par x 8 outputs/thread, taps amortized over 16 outputs,
// smem filter slab, double-buffered cp.async, persistent balanced grid) with
// DPB=16 / TG=21 geometry: 336-thread blocks, TT=336, 2 blocks/SM ->
// ~21 warps/SM (was 14). More warps fill the FFMA2 RF-bank (rt=3) gap
// cycles and LDS waits. Halo ratio drops 1.71x -> 1.24x.
//
// out[b,t,d] = sum_{i=0..19} filt[i,d]*x[b,t-(20-i)*2,d]
//            + filt[20,d]*x[b,t,d]
//            + sum_{j=0..19} filt[21+j,d]*x[b,t+1+2j,d],  zero-padded.

#define B_    32
#define T_    2000
#define DPAL  256       // d-pairs across all of D
#define DPB   16        // d-pairs per block
#define RT    8         // outputs per parity chunk
#define TG    21        // t-groups per block (16 t each)
#define NTH   (DPB * TG)               // 336 threads
#define TT    (16 * TG)                // 336 t-outputs per tile
#define NTILE 6                        // 6*336 = 2016 >= 2000
#define NSLAB (DPAL / DPB)             // 16
#define NUNIT (B_ * NSLAB * NTILE)     // 3072 work units
#define NBLK  296                      // 2 blocks x 148 SMs
#define ROWS  (TT + 80)                // 416 smem rows per tile
#define XWORDS (ROWS * DPB)            // 6656 u64 per buffer
#define XBYTES (XWORDS * 8)            // 53248 B
#define FWORDS (41 * DPB)              // 656 u64
#define SMEM_BYTES (2 * XBYTES + FWORDS * 8)   // 111744 B
#define CHUNKS (ROWS * 8)              // 3328 16B units per tile

__device__ __forceinline__ uint64_t f2fma(uint64_t a, uint64_t b, uint64_t c) {
    uint64_t r;
    asm("fma.rn.f32x2 %0, %1, %2, %3;" : "=l"(r) : "l"(a), "l"(b), "l"(c));
    return r;
}

__device__ __forceinline__ uint32_t smem_u32(const void* p) {
    uint32_t a;
    asm("{ .reg .u64 t; cvta.to.shared.u64 t, %1; cvt.u32.u64 %0, t; }"
        : "=r"(a) : "l"(p));
    return a;
}

__global__ __launch_bounds__(NTH, 2)
void fsmn_kernel(const float* __restrict__ x,
                 const float* __restrict__ filt,
                 float* __restrict__ out)
{
    extern __shared__ uint64_t sm[];   // [2][ROWS][DPB] x | [41][DPB] filt
    uint64_t* const sx = sm;
    uint64_t* const sf = sm + 2 * XWORDS;

    const int tid = threadIdx.x;
    const int bid = blockIdx.x;

    // Balanced contiguous partition of the 3072 units.
    const int lo = (int)(((long long)bid       * NUNIT) / NBLK);
    const int hi = (int)(((long long)(bid + 1) * NUNIT) / NBLK);

    const uint64_t* __restrict__ xu = reinterpret_cast<const uint64_t*>(x);
    uint64_t* __restrict__       ou = reinterpret_cast<uint64_t*>(out);
    const uint64_t* __restrict__ fu = reinterpret_cast<const uint64_t*>(filt);

    const uint32_t sbase = smem_u32(sx);
    const int dpl = tid & (DPB - 1);          // 0..15
    const int g   = tid >> 4;                 // 0..20 (16 t each)
    const uint64_t* __restrict__ sfp = sf + dpl;

    // Issue a tile prefetch for unit u into buffer buf.
    auto prefetch = [&](int buf, int u) {
        const int tile = u % NTILE;
        const int bs   = u / NTILE;
        const int slab = bs & (NSLAB - 1);
        const int bb   = bs >> 4;
        const uint64_t* __restrict__ xg =
            xu + (size_t)bb * T_ * DPAL + slab * DPB;
        const int tb = tile * TT;
        const uint32_t db = sbase + (uint32_t)buf * XBYTES;
#pragma unroll
        for (int k = 0; k < 10; ++k) {
            const int uu = tid + k * NTH;
            if (uu < CHUNKS) {
                const int row = uu >> 3;
                const int c8  = uu & 7;
                const int t   = tb - 40 + row;
                const char* gp =
                    reinterpret_cast<const char*>(xg + (size_t)t * DPAL)
                    + c8 * 16;
                const uint32_t dst = db + (uint32_t)(row * DPB) * 8 + c8 * 16;
                const int ok = (t >= 0 && t < T_) ? 16 : 0;
                asm volatile("cp.async.cg.shared.global [%0], [%1], 16, %2;"
                             :: "r"(dst), "l"(gp), "r"(ok) : "memory");
            }
        }
        asm volatile("cp.async.commit_group;" ::: "memory");
    };

    int prev_slab = -1;
    prefetch(0, lo);

    for (int u = lo; u < hi; ++u) {
        const int tile = u % NTILE;
        const int bs   = u / NTILE;
        const int slab = bs & (NSLAB - 1);
        const int bb   = bs >> 4;
        const int tb   = tile * TT;
        const int buf  = (u - lo) & 1;

        uint64_t* __restrict__ og =
            ou + (size_t)bb * T_ * DPAL + slab * DPB;

        if (u + 1 < hi) {
            prefetch(buf ^ 1, u + 1);
            asm volatile("cp.async.wait_group 1;" ::: "memory");
        } else {
            asm volatile("cp.async.wait_group 0;" ::: "memory");
        }

        // Refresh the filter slab in smem when the d-slab changes.
        if (slab != prev_slab) {
            const uint64_t* __restrict__ fg = fu + slab * DPB;
#pragma unroll
            for (int k = 0; k < 2; ++k) {
                const int i = tid + k * NTH;
                if (i < FWORDS)
                    sf[i] = fg[(size_t)(i >> 4) * DPAL + (i & (DPB - 1))];
            }
        }
        prev_slab = slab;
        __syncthreads();

        const uint64_t* __restrict__ sxp = sx + buf * XWORDS + dpl;

        uint64_t acc[16];                      // [par*8 + r]
#pragma unroll
        for (int z = 0; z < 16; ++z) acc[z] = 0ull;

        // ======== A phase: left+center taps filt[0..20], both parities =====
        {
            uint64_t fL[21];
#pragma unroll
            for (int c = 0; c < 21; ++c) fL[c] = sfp[c * DPB];
#pragma unroll
            for (int par = 0; par < 2; ++par) {
                const int rb = g * 16 + par;   // smem row of x[t0-40]
                uint64_t w[RT];
#pragma unroll
                for (int uu = 0; uu < RT; ++uu)
                    w[uu] = sxp[(rb + 2 * uu) * DPB];
#pragma unroll
                for (int c = 0; c < 21; ++c) {
#pragma unroll
                    for (int r = 0; r < RT; ++r)
                        acc[par * RT + r] = f2fma(fL[c], w[(c + r) & (RT - 1)],
                                                  acc[par * RT + r]);
                    if (c < 20)
                        w[c & (RT - 1)] = sxp[(rb + 2 * (c + RT)) * DPB];
                }
            }
        }

        // ======== B phase: right taps filt[21..40], both parities ==========
        {
            uint64_t fR[20];
#pragma unroll
            for (int c = 0; c < 20; ++c) fR[c] = sfp[(21 + c) * DPB];
#pragma unroll
            for (int par = 0; par < 2; ++par) {
                const int rb = g * 16 + par + 41; // smem row of x[t0+1]
                uint64_t w[RT];
#pragma unroll
                for (int uu = 0; uu < RT; ++uu)
                    w[uu] = sxp[(rb + 2 * uu) * DPB];
#pragma unroll
                for (int c = 0; c < 20; ++c) {
#pragma unroll
                    for (int r = 0; r < RT; ++r)
                        acc[par * RT + r] = f2fma(fR[c], w[(c + r) & (RT - 1)],
                                                  acc[par * RT + r]);
                    if (c < 19)
                        w[c & (RT - 1)] = sxp[(rb + 2 * (c + RT)) * DPB];
                }
            }
        }

        // -------- store 16 outputs (guard: tile 5 reaches t=2015) ----------
#pragma unroll
        for (int par = 0; par < 2; ++par) {
            const int t0 = tb + g * 16 + par;
#pragma unroll
            for (int r = 0; r < RT; ++r) {
                const int t = t0 + 2 * r;
                if (t < T_) og[(size_t)t * DPAL + dpl] = acc[par * RT + r];
            }
        }
        __syncthreads();   // protect smem buffers before next iteration
    }
}

extern "C" void kernel_launch(void* const* d_in, const int* in_sizes, int n_in,
                              void* d_out, int out_size)
{
    const float* x    = (const float*)d_in[0];   // [32, 2000, 512] f32
    const float* filt = (const float*)d_in[1];   // [41, 512] f32
    float* out        = (float*)d_out;           // [32, 2000, 512] f32

    cudaFuncSetAttribute(fsmn_kernel,
                         cudaFuncAttributeMaxDynamicSharedMemorySize,
                         SMEM_BYTES);

    fsmn_kernel<<<NBLK, NTH, SMEM_BYTES>>>(x, filt, out);
}